// round 4
// baseline (speedup 1.0000x reference)
#include <cuda_runtime.h>
#include <cstdint>

#define C_CLUST    64
#define NCOPY      16
#define ACC_STRIDE 17                      // 16 dims + 1 count slot
#define ACC_SIZE   (C_CLUST * ACC_STRIDE)  // 1088
#define P1_BLOCKS  (148 * 6)               // smem-limited to 6 blocks/SM (34.8KB each)

// Scratch (no allocations allowed -> __device__ globals)
__device__ float  g_acc[NCOPY][ACC_SIZE];
__device__ float  g_cnt[C_CLUST];
__device__ float  g_invCD[C_CLUST];           // 1 / (C * max(count,1))
__device__ float  g_means[C_CLUST * 16];      // [c][d]
__device__ float  g_meansT[16 * C_CLUST];     // [d][c]
__device__ float  g_var;

__device__ __forceinline__ void red_add_f32(float* addr, float v) {
    asm volatile("red.global.add.f32 [%0], %1;" :: "l"(addr), "f"(v) : "memory");
}

// ---------------------------------------------------------------- zero scratch
__global__ void k_zero() {
    int tid = blockIdx.x * blockDim.x + threadIdx.x;
    int stride = gridDim.x * blockDim.x;
    float* a = (float*)g_acc;
    for (int i = tid; i < NCOPY * ACC_SIZE; i += stride) a[i] = 0.f;
    if (tid == 0) g_var = 0.f;
}

// ---------------------------------------------------------------- pass 1
// Scalar-lane layout: lane = half*16 + d. The coalesced LDG.32 at
// feat[chunk*16 + it*32 + lane] delivers dim d of point (chunk + 2*it + half)
// straight to its accumulating lane -> NO transpose shuffles.
// Each warp owns a private acc[64][17] in shared; the only cross-lane hazard
// is the two halves hitting the same label, merged via one shfl_xor pair.
__global__ void __launch_bounds__(256) k_pass1(const float* __restrict__ feat,
                                               const int* __restrict__ labels,
                                               int npts) {
    __shared__ float s_acc[8][ACC_SIZE];

    const int wid  = threadIdx.x >> 5;
    const int lane = threadIdx.x & 31;
    float* acc = s_acc[wid];
    for (int i = lane; i < ACC_SIZE; i += 32) acc[i] = 0.f;
    __syncwarp();

    const int d    = lane & 15;
    const int half = lane >> 4;
    const int gw    = blockIdx.x * 8 + wid;
    const int nwarp = gridDim.x * 8;

    for (int chunk = gw * 32; chunk < npts; chunk += nwarp * 32) {
        int p = chunk + lane;
        int labv = (p < npts) ? labels[p] : -1;   // 32 labels, coalesced
        const float* fbase = feat + (size_t)chunk * 16;

        #pragma unroll
        for (int it = 0; it < 16; it++) {
            int labm = __shfl_sync(0xffffffffu, labv, 2 * it + half);
            int labo = __shfl_sync(0xffffffffu, labv, 2 * it + (half ^ 1));
            bool mine = (labm >= 0);
            float v = 0.f;
            if (mine) v = fbase[it * 32 + lane];  // 128B coalesced LDG.32
            float vo = __shfl_xor_sync(0xffffffffu, v, 16);

            bool dup = (labm == labo);            // both halves same cluster
            bool wr  = mine && !(dup && half == 0);
            float add = v + ((dup && half == 1) ? vo : 0.f);
            if (wr) {
                int a = labm * ACC_STRIDE + d;
                acc[a] += add;                    // scalar LDS+FADD+STS
                if (d == 0)
                    acc[labm * ACC_STRIDE + 16] += (dup ? 2.f : 1.f);
            }
            __syncwarp();
        }
    }

    // block reduce 8 warp copies -> 1 RED per element per block
    __syncthreads();
    const int copy = blockIdx.x & (NCOPY - 1);
    for (int idx = threadIdx.x; idx < ACC_SIZE; idx += 256) {
        float s = 0.f;
        #pragma unroll
        for (int w = 0; w < 8; w++) s += s_acc[w][idx];
        red_add_f32(&g_acc[copy][idx], s);
    }
}

// ---------------------------------------------------------------- means (1 block, 1024 thr)
__global__ void k_means() {
    __shared__ float s_c[C_CLUST];
    int t = threadIdx.x;
    if (t < C_CLUST) {
        float c = 0.f;
        #pragma unroll
        for (int k = 0; k < NCOPY; k++) c += g_acc[k][t * ACC_STRIDE + 16];
        g_cnt[t] = c;
        float sc = fmaxf(c, 1.f);
        s_c[t] = sc;
        g_invCD[t] = 1.f / ((float)C_CLUST * sc);
    }
    __syncthreads();
    int c = t >> 4, d = t & 15;
    float s = 0.f;
    #pragma unroll
    for (int k = 0; k < NCOPY; k++) s += g_acc[k][c * ACC_STRIDE + d];
    float m = s / s_c[c];
    g_means[c * 16 + d]  = m;
    g_meansT[d * 64 + c] = m;
}

// ---------------------------------------------------------------- pass 2: variance hinge
// var_loss = sum_points hinge(||x - mu + eps|| - 0.5)^2 / (C * count[label])
// (unchanged from round 3: 49.2us, DRAM 70.9%)
__global__ void __launch_bounds__(256) k_pass2(const float4* __restrict__ feat4,
                                               const int* __restrict__ labels,
                                               int n4) {
    __shared__ float s_mT[16][C_CLUST + 1];
    __shared__ float s_inv[C_CLUST];
    __shared__ float s_w[8];

    for (int i = threadIdx.x; i < 16 * C_CLUST; i += 256)
        s_mT[i >> 6][i & 63] = g_meansT[i];
    if (threadIdx.x < C_CLUST) s_inv[threadIdx.x] = g_invCD[threadIdx.x];
    __syncthreads();

    const int lane = threadIdx.x & 31;
    const int g    = threadIdx.x & 3;
    const int d0   = g * 4;
    const int stride = gridDim.x * 512;
    float local = 0.f;

    for (int j = blockIdx.x * 512 + threadIdx.x; j - lane < n4; j += stride) {
        int  jb = j + 256;
        bool a1 = (j < n4), a2 = (jb < n4);
        float4 v1, v2;
        int l1 = 0, l2 = 0;
        if (a1) { l1 = labels[j  >> 2]; v1 = feat4[j];  }
        if (a2) { l2 = labels[jb >> 2]; v2 = feat4[jb]; }

        float p1 = 0.f, p2 = 0.f;
        if (a1) {
            float dx = v1.x - s_mT[d0 + 0][l1] + 1e-8f;
            float dy = v1.y - s_mT[d0 + 1][l1] + 1e-8f;
            float dz = v1.z - s_mT[d0 + 2][l1] + 1e-8f;
            float dw = v1.w - s_mT[d0 + 3][l1] + 1e-8f;
            p1 = fmaf(dx, dx, fmaf(dy, dy, fmaf(dz, dz, dw * dw)));
        }
        if (a2) {
            float dx = v2.x - s_mT[d0 + 0][l2] + 1e-8f;
            float dy = v2.y - s_mT[d0 + 1][l2] + 1e-8f;
            float dz = v2.z - s_mT[d0 + 2][l2] + 1e-8f;
            float dw = v2.w - s_mT[d0 + 3][l2] + 1e-8f;
            p2 = fmaf(dx, dx, fmaf(dy, dy, fmaf(dz, dz, dw * dw)));
        }
        p1 += __shfl_xor_sync(0xffffffffu, p1, 1);
        p1 += __shfl_xor_sync(0xffffffffu, p1, 2);
        p2 += __shfl_xor_sync(0xffffffffu, p2, 1);
        p2 += __shfl_xor_sync(0xffffffffu, p2, 2);
        if (g == 0) {
            if (a1) {
                float h = fmaxf(sqrtf(p1) - 0.5f, 0.f);
                local += h * h * s_inv[l1];
            }
            if (a2) {
                float h = fmaxf(sqrtf(p2) - 0.5f, 0.f);
                local += h * h * s_inv[l2];
            }
        }
    }

    #pragma unroll
    for (int o = 16; o > 0; o >>= 1)
        local += __shfl_xor_sync(0xffffffffu, local, o);
    if (lane == 0) s_w[threadIdx.x >> 5] = local;
    __syncthreads();
    if (threadIdx.x == 0) {
        float s = 0.f;
        #pragma unroll
        for (int w = 0; w < 8; w++) s += s_w[w];
        red_add_f32(&g_var, s);
    }
}

// ---------------------------------------------------------------- finalize (1 block, 256 thr)
__global__ void k_final(float* __restrict__ out) {
    __shared__ float s_m[C_CLUST][16];
    __shared__ float s_red[256];
    int t = threadIdx.x;
    for (int i = t; i < C_CLUST * 16; i += 256)
        ((float*)s_m)[i] = g_means[i];
    __syncthreads();

    float regp = 0.f;
    if (t < C_CLUST) {
        float s = 0.f;
        #pragma unroll
        for (int d = 0; d < 16; d++) {
            float v = s_m[t][d] + 1e-8f;
            s += v * v;
        }
        regp = sqrtf(s);
    }

    float dl = 0.f;
    for (int p = t; p < C_CLUST * C_CLUST; p += 256) {
        int i = p >> 6, jj = p & 63;
        if (i != jj) {
            float s = 0.f;
            #pragma unroll
            for (int d = 0; d < 16; d++) {
                float df = s_m[i][d] - s_m[jj][d] + 1e-8f;
                s += df * df;
            }
            float pd = sqrtf(s);
            float h = fmaxf(3.0f - pd, 0.f);   // 2 * DELTA_DIST
            dl += h * h;
        }
    }

    s_red[t] = dl; __syncthreads();
    for (int o = 128; o > 0; o >>= 1) { if (t < o) s_red[t] += s_red[t + o]; __syncthreads(); }
    float dist_loss = s_red[0] / (float)(C_CLUST * (C_CLUST - 1));
    __syncthreads();

    s_red[t] = regp; __syncthreads();
    for (int o = 128; o > 0; o >>= 1) { if (t < o) s_red[t] += s_red[t + o]; __syncthreads(); }
    float reg_loss = s_red[0] / (float)C_CLUST;

    if (t == 0) {
        float var_loss = g_var;
        out[0] = var_loss + dist_loss + 0.001f * reg_loss;
        out[1] = var_loss;
        out[2] = dist_loss;
        out[3] = reg_loss;
    }
}

// ---------------------------------------------------------------- launch
extern "C" void kernel_launch(void* const* d_in, const int* in_sizes, int n_in,
                              void* d_out, int out_size) {
    const float*  feat   = (const float*)d_in[0];
    const int*    labels = (const int*)d_in[1];
    int N  = in_sizes[1];     // number of points
    int n4 = N * 4;           // float4 count (D=16)

    k_zero <<<68, 256>>>();
    k_pass1<<<P1_BLOCKS, 256>>>(feat, labels, N);
    k_means<<<1, 1024>>>();
    k_pass2<<<148 * 8, 256>>>((const float4*)feat, labels, n4);
    k_final<<<1, 256>>>((float*)d_out);
}

// round 5
// speedup vs baseline: 2.2461x; 2.2461x over previous
#include <cuda_runtime.h>
#include <cstdint>

#define C_CLUST    64
#define NCOPY      16
#define ACC_STRIDE 17                      // 16 dims + 1 count slot
#define ACC_SIZE   (C_CLUST * ACC_STRIDE)  // 1088
#define P1_BLOCKS  (148 * 5)               // 43.5KB smem/block -> 5 blocks/SM, 1 wave

// Scratch (no allocations allowed -> __device__ globals)
__device__ float  g_acc[NCOPY][ACC_SIZE];
__device__ float  g_cnt[C_CLUST];
__device__ float  g_invCD[C_CLUST];           // 1 / (C * max(count,1))
__device__ float  g_means[C_CLUST * 16];      // [c][d]
__device__ float  g_meansT[16 * C_CLUST];     // [d][c]
__device__ float  g_var;

__device__ __forceinline__ void red_add_f32(float* addr, float v) {
    asm volatile("red.global.add.f32 [%0], %1;" :: "l"(addr), "f"(v) : "memory");
}

// ---------------------------------------------------------------- zero scratch
__global__ void k_zero() {
    int tid = blockIdx.x * blockDim.x + threadIdx.x;
    int stride = gridDim.x * blockDim.x;
    float* a = (float*)g_acc;
    for (int i = tid; i < NCOPY * ACC_SIZE; i += stride) a[i] = 0.f;
    if (tid == 0) g_var = 0.f;
}

// ---------------------------------------------------------------- pass 1
// Per-warp private acc[64][17] in shared (no atomics).
// Loads are UNCONDITIONAL (full-chunk loop bound only) so they pipeline.
// Transpose goes through a double-buffered smem staging tile:
//   STS.128 once, then each round one conflict-free LDS.32 delivers dim d of
//   point 2r+half straight to lane (half,d). Cross-half same-label collision
//   merged via one shfl_xor pair (round-2 proven logic).
__global__ void __launch_bounds__(256) k_pass1(const float4* __restrict__ feat4,
                                               const float*  __restrict__ feat,
                                               const int* __restrict__ labels,
                                               int npts) {
    __shared__ float  s_acc[8][ACC_SIZE];
    __shared__ float4 s_stg[8][2][32];
    __shared__ int    s_lab[8][2][8];

    const int wid  = threadIdx.x >> 5;
    const int lane = threadIdx.x & 31;
    float* acc = s_acc[wid];
    for (int i = lane; i < ACC_SIZE; i += 32) acc[i] = 0.f;

    const int d    = lane & 15;
    const int half = lane >> 4;
    const int gw    = blockIdx.x * 8 + wid;
    const int nwarp = gridDim.x * 8;

    int pb = 0;
    for (int base = gw * 8; base + 8 <= npts; base += nwarp * 8, pb ^= 1) {
        float4 f = feat4[base * 4 + lane];        // unconditional, pipelines
        int lb = 0;
        if (lane < 8) lb = labels[base + lane];   // static predicate, coalesced
        s_stg[wid][pb][lane] = f;
        if (lane < 8) s_lab[wid][pb][lane] = lb;
        __syncwarp();                             // cross-lane visibility

        const float* stg = (const float*)s_stg[wid][pb];
        const int*   slb = s_lab[wid][pb];
        #pragma unroll
        for (int r = 0; r < 4; r++) {
            int   labm = slb[2 * r + half];       // broadcast LDS
            float v    = stg[r * 32 + lane];      // conflict-free LDS.32
            int   labo = __shfl_xor_sync(0xffffffffu, labm, 16);
            float vo   = __shfl_xor_sync(0xffffffffu, v, 16);
            bool dup = (labm == labo);
            bool wr  = !(dup && half == 0);       // lower half defers to upper
            float add = v + ((dup && half == 1) ? vo : 0.f);
            if (wr) {
                acc[labm * ACC_STRIDE + d] += add;
                if (d == 0)
                    acc[labm * ACC_STRIDE + 16] += (dup ? 2.f : 1.f);
            }
        }
    }

    // tail (npts % 8 points): one warp, one point at a time, lanes 0..16
    if (gw == 0) {
        for (int p = npts & ~7; p < npts; p++) {
            int lb = labels[p];
            if (lane <= 16)
                acc[lb * ACC_STRIDE + lane] +=
                    (lane < 16) ? feat[(size_t)p * 16 + lane] : 1.f;
        }
    }

    // block reduce 8 warp copies -> 1 RED per element per block
    __syncthreads();
    const int copy = blockIdx.x & (NCOPY - 1);
    for (int idx = threadIdx.x; idx < ACC_SIZE; idx += 256) {
        float s = 0.f;
        #pragma unroll
        for (int w = 0; w < 8; w++) s += s_acc[w][idx];
        red_add_f32(&g_acc[copy][idx], s);
    }
}

// ---------------------------------------------------------------- means (1 block, 1024 thr)
__global__ void k_means() {
    __shared__ float s_c[C_CLUST];
    int t = threadIdx.x;
    if (t < C_CLUST) {
        float c = 0.f;
        #pragma unroll
        for (int k = 0; k < NCOPY; k++) c += g_acc[k][t * ACC_STRIDE + 16];
        g_cnt[t] = c;
        float sc = fmaxf(c, 1.f);
        s_c[t] = sc;
        g_invCD[t] = 1.f / ((float)C_CLUST * sc);
    }
    __syncthreads();
    int c = t >> 4, d = t & 15;
    float s = 0.f;
    #pragma unroll
    for (int k = 0; k < NCOPY; k++) s += g_acc[k][c * ACC_STRIDE + d];
    float m = s / s_c[c];
    g_means[c * 16 + d]  = m;
    g_meansT[d * 64 + c] = m;
}

// ---------------------------------------------------------------- pass 2 (round-3 verbatim: 49.2us)
__global__ void __launch_bounds__(256) k_pass2(const float4* __restrict__ feat4,
                                               const int* __restrict__ labels,
                                               int n4) {
    __shared__ float s_mT[16][C_CLUST + 1];
    __shared__ float s_inv[C_CLUST];
    __shared__ float s_w[8];

    for (int i = threadIdx.x; i < 16 * C_CLUST; i += 256)
        s_mT[i >> 6][i & 63] = g_meansT[i];
    if (threadIdx.x < C_CLUST) s_inv[threadIdx.x] = g_invCD[threadIdx.x];
    __syncthreads();

    const int lane = threadIdx.x & 31;
    const int g    = threadIdx.x & 3;
    const int d0   = g * 4;
    const int stride = gridDim.x * 512;
    float local = 0.f;

    for (int j = blockIdx.x * 512 + threadIdx.x; j - lane < n4; j += stride) {
        int  jb = j + 256;
        bool a1 = (j < n4), a2 = (jb < n4);
        float4 v1, v2;
        int l1 = 0, l2 = 0;
        if (a1) { l1 = labels[j  >> 2]; v1 = feat4[j];  }
        if (a2) { l2 = labels[jb >> 2]; v2 = feat4[jb]; }

        float p1 = 0.f, p2 = 0.f;
        if (a1) {
            float dx = v1.x - s_mT[d0 + 0][l1] + 1e-8f;
            float dy = v1.y - s_mT[d0 + 1][l1] + 1e-8f;
            float dz = v1.z - s_mT[d0 + 2][l1] + 1e-8f;
            float dw = v1.w - s_mT[d0 + 3][l1] + 1e-8f;
            p1 = fmaf(dx, dx, fmaf(dy, dy, fmaf(dz, dz, dw * dw)));
        }
        if (a2) {
            float dx = v2.x - s_mT[d0 + 0][l2] + 1e-8f;
            float dy = v2.y - s_mT[d0 + 1][l2] + 1e-8f;
            float dz = v2.z - s_mT[d0 + 2][l2] + 1e-8f;
            float dw = v2.w - s_mT[d0 + 3][l2] + 1e-8f;
            p2 = fmaf(dx, dx, fmaf(dy, dy, fmaf(dz, dz, dw * dw)));
        }
        p1 += __shfl_xor_sync(0xffffffffu, p1, 1);
        p1 += __shfl_xor_sync(0xffffffffu, p1, 2);
        p2 += __shfl_xor_sync(0xffffffffu, p2, 1);
        p2 += __shfl_xor_sync(0xffffffffu, p2, 2);
        if (g == 0) {
            if (a1) {
                float h = fmaxf(sqrtf(p1) - 0.5f, 0.f);
                local += h * h * s_inv[l1];
            }
            if (a2) {
                float h = fmaxf(sqrtf(p2) - 0.5f, 0.f);
                local += h * h * s_inv[l2];
            }
        }
    }

    #pragma unroll
    for (int o = 16; o > 0; o >>= 1)
        local += __shfl_xor_sync(0xffffffffu, local, o);
    if (lane == 0) s_w[threadIdx.x >> 5] = local;
    __syncthreads();
    if (threadIdx.x == 0) {
        float s = 0.f;
        #pragma unroll
        for (int w = 0; w < 8; w++) s += s_w[w];
        red_add_f32(&g_var, s);
    }
}

// ---------------------------------------------------------------- finalize (1 block, 256 thr)
__global__ void k_final(float* __restrict__ out) {
    __shared__ float s_m[C_CLUST][16];
    __shared__ float s_red[256];
    int t = threadIdx.x;
    for (int i = t; i < C_CLUST * 16; i += 256)
        ((float*)s_m)[i] = g_means[i];
    __syncthreads();

    float regp = 0.f;
    if (t < C_CLUST) {
        float s = 0.f;
        #pragma unroll
        for (int d = 0; d < 16; d++) {
            float v = s_m[t][d] + 1e-8f;
            s += v * v;
        }
        regp = sqrtf(s);
    }

    float dl = 0.f;
    for (int p = t; p < C_CLUST * C_CLUST; p += 256) {
        int i = p >> 6, jj = p & 63;
        if (i != jj) {
            float s = 0.f;
            #pragma unroll
            for (int d = 0; d < 16; d++) {
                float df = s_m[i][d] - s_m[jj][d] + 1e-8f;
                s += df * df;
            }
            float pd = sqrtf(s);
            float h = fmaxf(3.0f - pd, 0.f);   // 2 * DELTA_DIST
            dl += h * h;
        }
    }

    s_red[t] = dl; __syncthreads();
    for (int o = 128; o > 0; o >>= 1) { if (t < o) s_red[t] += s_red[t + o]; __syncthreads(); }
    float dist_loss = s_red[0] / (float)(C_CLUST * (C_CLUST - 1));
    __syncthreads();

    s_red[t] = regp; __syncthreads();
    for (int o = 128; o > 0; o >>= 1) { if (t < o) s_red[t] += s_red[t + o]; __syncthreads(); }
    float reg_loss = s_red[0] / (float)C_CLUST;

    if (t == 0) {
        float var_loss = g_var;
        out[0] = var_loss + dist_loss + 0.001f * reg_loss;
        out[1] = var_loss;
        out[2] = dist_loss;
        out[3] = reg_loss;
    }
}

// ---------------------------------------------------------------- launch
extern "C" void kernel_launch(void* const* d_in, const int* in_sizes, int n_in,
                              void* d_out, int out_size) {
    const float*  feat   = (const float*)d_in[0];
    const int*    labels = (const int*)d_in[1];
    int N  = in_sizes[1];     // number of points
    int n4 = N * 4;           // float4 count (D=16)

    k_zero <<<68, 256>>>();
    k_pass1<<<P1_BLOCKS, 256>>>((const float4*)feat, feat, labels, N);
    k_means<<<1, 1024>>>();
    k_pass2<<<148 * 8, 256>>>((const float4*)feat, labels, n4);
    k_final<<<1, 256>>>((float*)d_out);
}

// round 6
// speedup vs baseline: 2.8526x; 1.2700x over previous
#include <cuda_runtime.h>
#include <cstdint>

#define C_CLUST    64
#define NCOPY      16
#define ACC_STRIDE 17                      // 16 dims + 1 count slot
#define ACC_SIZE   (C_CLUST * ACC_STRIDE)  // 1088
#define P1_WARPS   4                       // warps per pass1 block
#define P1_BLOCKS  (148 * 6)               // 34.8KB smem -> 6 blocks/SM

// Scratch (no allocations allowed -> __device__ globals)
__device__ float  g_acc[NCOPY][ACC_SIZE];
__device__ float  g_cnt[C_CLUST];
__device__ float  g_invCD[C_CLUST];           // 1 / (C * max(count,1))
__device__ float  g_means[C_CLUST * 16];      // [c][d]
__device__ float  g_meansT[16 * C_CLUST];     // [d][c]
__device__ float  g_var;

__device__ __forceinline__ void red_add_f32(float* addr, float v) {
    asm volatile("red.global.add.f32 [%0], %1;" :: "l"(addr), "f"(v) : "memory");
}

// ---------------------------------------------------------------- zero scratch
__global__ void k_zero() {
    int tid = blockIdx.x * blockDim.x + threadIdx.x;
    int stride = gridDim.x * blockDim.x;
    float* a = (float*)g_acc;
    for (int i = tid; i < NCOPY * ACC_SIZE; i += stride) a[i] = 0.f;
    if (tid == 0) g_var = 0.f;
}

// ---------------------------------------------------------------- pass 1
// Scalar-lane mapping, zero transpose: lane = half*16 + d, and the coalesced
// LDG.32 at feat[chunk*16 + it*32 + lane] IS dim d of point (2*it + half).
// All 16 loads hoisted & unconditional -> MLP=16 (round-4's predication bug fixed).
// Each half-warp owns a PRIVATE acc[64][17] copy -> no collisions, no merge
// shuffles, no syncwarp. Per round: 1 shfl (label) + scalar LDS/FADD/STS.
__global__ void __launch_bounds__(128) k_pass1(const float* __restrict__ feat,
                                               const int* __restrict__ labels,
                                               int npts) {
    __shared__ float s_acc[P1_WARPS * 2][ACC_SIZE];   // 34816 B

    const int wid  = threadIdx.x >> 5;
    const int lane = threadIdx.x & 31;
    const int half = lane >> 4;
    const int d    = lane & 15;
    float* acc = s_acc[wid * 2 + half];

    for (int i = threadIdx.x; i < P1_WARPS * 2 * ACC_SIZE; i += 128)
        ((float*)s_acc)[i] = 0.f;
    __syncthreads();

    const int gw    = blockIdx.x * P1_WARPS + wid;
    const int nwarp = gridDim.x * P1_WARPS;

    for (int chunk = gw * 32; chunk + 32 <= npts; chunk += nwarp * 32) {
        int labv = labels[chunk + lane];              // 32 labels, coalesced
        const float* fb = feat + (size_t)chunk * 16;
        float v[16];
        #pragma unroll
        for (int it = 0; it < 16; it++)               // 16 independent LDG.32
            v[it] = fb[it * 32 + lane];

        #pragma unroll
        for (int it = 0; it < 16; it++) {
            int labm = __shfl_sync(0xffffffffu, labv, 2 * it + half);
            float* a = &acc[labm * ACC_STRIDE];
            a[d] += v[it];                            // private copy: race-free
            if (d == 0) a[16] += 1.f;                 // count (lanes 0 and 16)
        }
    }

    // tail (npts % 32): one warp, scalar per point (empty for N=4M)
    if (gw == 0) {
        float* a0 = s_acc[0];
        for (int p = npts & ~31; p < npts; p++) {
            int lb = labels[p];
            if (lane < 16) a0[lb * ACC_STRIDE + lane] += feat[(size_t)p * 16 + lane];
            if (lane == 0) a0[lb * ACC_STRIDE + 16] += 1.f;
        }
    }

    // block reduce 8 copies -> 1 RED per element per block
    __syncthreads();
    const int copy = blockIdx.x & (NCOPY - 1);
    for (int idx = threadIdx.x; idx < ACC_SIZE; idx += 128) {
        float s = 0.f;
        #pragma unroll
        for (int w = 0; w < P1_WARPS * 2; w++) s += s_acc[w][idx];
        red_add_f32(&g_acc[copy][idx], s);
    }
}

// ---------------------------------------------------------------- means (1 block, 1024 thr)
__global__ void k_means() {
    __shared__ float s_c[C_CLUST];
    int t = threadIdx.x;
    if (t < C_CLUST) {
        float c = 0.f;
        #pragma unroll
        for (int k = 0; k < NCOPY; k++) c += g_acc[k][t * ACC_STRIDE + 16];
        g_cnt[t] = c;
        float sc = fmaxf(c, 1.f);
        s_c[t] = sc;
        g_invCD[t] = 1.f / ((float)C_CLUST * sc);
    }
    __syncthreads();
    int c = t >> 4, d = t & 15;
    float s = 0.f;
    #pragma unroll
    for (int k = 0; k < NCOPY; k++) s += g_acc[k][c * ACC_STRIDE + d];
    float m = s / s_c[c];
    g_means[c * 16 + d]  = m;
    g_meansT[d * 64 + c] = m;
}

// ---------------------------------------------------------------- pass 2 (round-3 verbatim: 49.2us, DRAM 70.8%)
__global__ void __launch_bounds__(256) k_pass2(const float4* __restrict__ feat4,
                                               const int* __restrict__ labels,
                                               int n4) {
    __shared__ float s_mT[16][C_CLUST + 1];
    __shared__ float s_inv[C_CLUST];
    __shared__ float s_w[8];

    for (int i = threadIdx.x; i < 16 * C_CLUST; i += 256)
        s_mT[i >> 6][i & 63] = g_meansT[i];
    if (threadIdx.x < C_CLUST) s_inv[threadIdx.x] = g_invCD[threadIdx.x];
    __syncthreads();

    const int lane = threadIdx.x & 31;
    const int g    = threadIdx.x & 3;
    const int d0   = g * 4;
    const int stride = gridDim.x * 512;
    float local = 0.f;

    for (int j = blockIdx.x * 512 + threadIdx.x; j - lane < n4; j += stride) {
        int  jb = j + 256;
        bool a1 = (j < n4), a2 = (jb < n4);
        float4 v1, v2;
        int l1 = 0, l2 = 0;
        if (a1) { l1 = labels[j  >> 2]; v1 = feat4[j];  }
        if (a2) { l2 = labels[jb >> 2]; v2 = feat4[jb]; }

        float p1 = 0.f, p2 = 0.f;
        if (a1) {
            float dx = v1.x - s_mT[d0 + 0][l1] + 1e-8f;
            float dy = v1.y - s_mT[d0 + 1][l1] + 1e-8f;
            float dz = v1.z - s_mT[d0 + 2][l1] + 1e-8f;
            float dw = v1.w - s_mT[d0 + 3][l1] + 1e-8f;
            p1 = fmaf(dx, dx, fmaf(dy, dy, fmaf(dz, dz, dw * dw)));
        }
        if (a2) {
            float dx = v2.x - s_mT[d0 + 0][l2] + 1e-8f;
            float dy = v2.y - s_mT[d0 + 1][l2] + 1e-8f;
            float dz = v2.z - s_mT[d0 + 2][l2] + 1e-8f;
            float dw = v2.w - s_mT[d0 + 3][l2] + 1e-8f;
            p2 = fmaf(dx, dx, fmaf(dy, dy, fmaf(dz, dz, dw * dw)));
        }
        p1 += __shfl_xor_sync(0xffffffffu, p1, 1);
        p1 += __shfl_xor_sync(0xffffffffu, p1, 2);
        p2 += __shfl_xor_sync(0xffffffffu, p2, 1);
        p2 += __shfl_xor_sync(0xffffffffu, p2, 2);
        if (g == 0) {
            if (a1) {
                float h = fmaxf(sqrtf(p1) - 0.5f, 0.f);
                local += h * h * s_inv[l1];
            }
            if (a2) {
                float h = fmaxf(sqrtf(p2) - 0.5f, 0.f);
                local += h * h * s_inv[l2];
            }
        }
    }

    #pragma unroll
    for (int o = 16; o > 0; o >>= 1)
        local += __shfl_xor_sync(0xffffffffu, local, o);
    if (lane == 0) s_w[threadIdx.x >> 5] = local;
    __syncthreads();
    if (threadIdx.x == 0) {
        float s = 0.f;
        #pragma unroll
        for (int w = 0; w < 8; w++) s += s_w[w];
        red_add_f32(&g_var, s);
    }
}

// ---------------------------------------------------------------- finalize (1 block, 256 thr)
__global__ void k_final(float* __restrict__ out) {
    __shared__ float s_m[C_CLUST][16];
    __shared__ float s_red[256];
    int t = threadIdx.x;
    for (int i = t; i < C_CLUST * 16; i += 256)
        ((float*)s_m)[i] = g_means[i];
    __syncthreads();

    float regp = 0.f;
    if (t < C_CLUST) {
        float s = 0.f;
        #pragma unroll
        for (int d = 0; d < 16; d++) {
            float v = s_m[t][d] + 1e-8f;
            s += v * v;
        }
        regp = sqrtf(s);
    }

    float dl = 0.f;
    for (int p = t; p < C_CLUST * C_CLUST; p += 256) {
        int i = p >> 6, jj = p & 63;
        if (i != jj) {
            float s = 0.f;
            #pragma unroll
            for (int d = 0; d < 16; d++) {
                float df = s_m[i][d] - s_m[jj][d] + 1e-8f;
                s += df * df;
            }
            float pd = sqrtf(s);
            float h = fmaxf(3.0f - pd, 0.f);   // 2 * DELTA_DIST
            dl += h * h;
        }
    }

    s_red[t] = dl; __syncthreads();
    for (int o = 128; o > 0; o >>= 1) { if (t < o) s_red[t] += s_red[t + o]; __syncthreads(); }
    float dist_loss = s_red[0] / (float)(C_CLUST * (C_CLUST - 1));
    __syncthreads();

    s_red[t] = regp; __syncthreads();
    for (int o = 128; o > 0; o >>= 1) { if (t < o) s_red[t] += s_red[t + o]; __syncthreads(); }
    float reg_loss = s_red[0] / (float)C_CLUST;

    if (t == 0) {
        float var_loss = g_var;
        out[0] = var_loss + dist_loss + 0.001f * reg_loss;
        out[1] = var_loss;
        out[2] = dist_loss;
        out[3] = reg_loss;
    }
}

// ---------------------------------------------------------------- launch
extern "C" void kernel_launch(void* const* d_in, const int* in_sizes, int n_in,
                              void* d_out, int out_size) {
    const float*  feat   = (const float*)d_in[0];
    const int*    labels = (const int*)d_in[1];
    int N  = in_sizes[1];     // number of points
    int n4 = N * 4;           // float4 count (D=16)

    k_zero <<<68, 256>>>();
    k_pass1<<<P1_BLOCKS, 128>>>(feat, labels, N);
    k_means<<<1, 1024>>>();
    k_pass2<<<148 * 8, 256>>>((const float4*)feat, labels, n4);
    k_final<<<1, 256>>>((float*)d_out);
}

// round 7
// speedup vs baseline: 3.1153x; 1.0921x over previous
#include <cuda_runtime.h>
#include <cstdint>

#define C_CLUST    64
#define NCOPY      16
#define ACC_STRIDE 17                      // global scratch: 16 dims + 1 count
#define ACC_SIZE   (C_CLUST * ACC_STRIDE)  // 1088
#define P1_WARPS   4
#define P1_BLOCKS  (148 * 6)

// Scratch (no allocations allowed -> __device__ globals)
__device__ float  g_acc[NCOPY][ACC_SIZE];
__device__ float  g_cnt[C_CLUST];
__device__ float  g_invCD[C_CLUST];           // 1 / (C * max(count,1))
__device__ float  g_means[C_CLUST * 16];      // [c][d]
__device__ float  g_meansT[16 * C_CLUST];     // [d][c]
__device__ float  g_var;

__device__ __forceinline__ void red_add_f32(float* addr, float v) {
    asm volatile("red.global.add.f32 [%0], %1;" :: "l"(addr), "f"(v) : "memory");
}

// ---------------------------------------------------------------- pass 1
// Scalar-lane mapping (lane = half*16 + d): the coalesced LDG.32 at
// feat[chunk*16 + it*32 + lane] IS dim d of point (2*it + half). Loads hoisted
// & unconditional -> MLP=16.
// Accumulator: per-warp acc[64][32]; half0 owns cols 0..15, half1 cols 16..31.
//   -> banks disjoint (0-15 vs 16-31): conflict-free, and no address aliasing.
// Counts: ONE match_any per chunk on each lane's own label (leaders add popc),
// not 16 predicated RMW chains.
__global__ void __launch_bounds__(128) k_pass1(const float* __restrict__ feat,
                                               const int* __restrict__ labels,
                                               int npts) {
    __shared__ float s_acc[P1_WARPS][C_CLUST * 32];   // 32 KB
    __shared__ float s_cnt[P1_WARPS][C_CLUST];        // 1 KB

    const int wid  = threadIdx.x >> 5;
    const int lane = threadIdx.x & 31;
    // base points at this lane's private column: col = half*16 + d = lane
    float* accL = s_acc[wid] + lane;
    float* cntW = s_cnt[wid];

    for (int i = threadIdx.x; i < P1_WARPS * C_CLUST * 32; i += 128)
        ((float*)s_acc)[i] = 0.f;
    for (int i = threadIdx.x; i < P1_WARPS * C_CLUST; i += 128)
        ((float*)s_cnt)[i] = 0.f;
    __syncthreads();

    const int half  = lane >> 4;
    const int gw    = blockIdx.x * P1_WARPS + wid;
    const int nwarp = gridDim.x * P1_WARPS;

    for (int chunk = gw * 32; chunk + 32 <= npts; chunk += nwarp * 32) {
        int labv = labels[chunk + lane];              // 32 labels, coalesced
        const float* fb = feat + (size_t)chunk * 16;
        float v[16];
        #pragma unroll
        for (int it = 0; it < 16; it++)               // 16 independent LDG.32
            v[it] = fb[it * 32 + lane];

        #pragma unroll
        for (int it = 0; it < 16; it++) {
            int labm = __shfl_sync(0xffffffffu, labv, 2 * it + half);
            accL[labm * 32] += v[it];                 // bank-disjoint, alias-free
        }

        // counts: dedup whole warp once per chunk
        unsigned mm = __match_any_sync(0xffffffffu, labv);
        if ((mm & ((1u << lane) - 1u)) == 0)          // leader per distinct label
            cntW[labv] += (float)__popc(mm);
    }

    // tail (npts % 32): warp 0 of block 0, scalar per point
    if (gw == 0) {
        float* a0 = s_acc[0];
        for (int p = npts & ~31; p < npts; p++) {
            int lb = labels[p];
            if (lane < 16) a0[lb * 32 + lane] += feat[(size_t)p * 16 + lane];
            if (lane == 0) s_cnt[0][lb] += 1.f;
        }
    }

    // block reduce 4 warp copies (merging the two half-columns) -> RED flush
    __syncthreads();
    const int copy = blockIdx.x & (NCOPY - 1);
    for (int idx = threadIdx.x; idx < C_CLUST * 16; idx += 128) {
        int c = idx >> 4, d = idx & 15;
        float s = 0.f;
        #pragma unroll
        for (int w = 0; w < P1_WARPS; w++)
            s += s_acc[w][c * 32 + d] + s_acc[w][c * 32 + 16 + d];
        red_add_f32(&g_acc[copy][c * ACC_STRIDE + d], s);
    }
    for (int c = threadIdx.x; c < C_CLUST; c += 128) {
        float s = 0.f;
        #pragma unroll
        for (int w = 0; w < P1_WARPS; w++) s += s_cnt[w][c];
        red_add_f32(&g_acc[copy][c * ACC_STRIDE + 16], s);
    }
}

// ---------------------------------------------------------------- means (1 block, 1024 thr)
__global__ void k_means() {
    __shared__ float s_c[C_CLUST];
    int t = threadIdx.x;
    if (t == 0) g_var = 0.f;                 // replaces k_zero's g_var init
    if (t < C_CLUST) {
        float c = 0.f;
        #pragma unroll
        for (int k = 0; k < NCOPY; k++) c += g_acc[k][t * ACC_STRIDE + 16];
        g_cnt[t] = c;
        float sc = fmaxf(c, 1.f);
        s_c[t] = sc;
        g_invCD[t] = 1.f / ((float)C_CLUST * sc);
    }
    __syncthreads();
    int c = t >> 4, d = t & 15;
    float s = 0.f;
    #pragma unroll
    for (int k = 0; k < NCOPY; k++) s += g_acc[k][c * ACC_STRIDE + d];
    float m = s / s_c[c];
    g_means[c * 16 + d]  = m;
    g_meansT[d * 64 + c] = m;
}

// ---------------------------------------------------------------- pass 2 (round-3 verbatim: 49.2us, DRAM 70.8%)
__global__ void __launch_bounds__(256) k_pass2(const float4* __restrict__ feat4,
                                               const int* __restrict__ labels,
                                               int n4) {
    __shared__ float s_mT[16][C_CLUST + 1];
    __shared__ float s_inv[C_CLUST];
    __shared__ float s_w[8];

    for (int i = threadIdx.x; i < 16 * C_CLUST; i += 256)
        s_mT[i >> 6][i & 63] = g_meansT[i];
    if (threadIdx.x < C_CLUST) s_inv[threadIdx.x] = g_invCD[threadIdx.x];
    __syncthreads();

    const int lane = threadIdx.x & 31;
    const int g    = threadIdx.x & 3;
    const int d0   = g * 4;
    const int stride = gridDim.x * 512;
    float local = 0.f;

    for (int j = blockIdx.x * 512 + threadIdx.x; j - lane < n4; j += stride) {
        int  jb = j + 256;
        bool a1 = (j < n4), a2 = (jb < n4);
        float4 v1, v2;
        int l1 = 0, l2 = 0;
        if (a1) { l1 = labels[j  >> 2]; v1 = feat4[j];  }
        if (a2) { l2 = labels[jb >> 2]; v2 = feat4[jb]; }

        float p1 = 0.f, p2 = 0.f;
        if (a1) {
            float dx = v1.x - s_mT[d0 + 0][l1] + 1e-8f;
            float dy = v1.y - s_mT[d0 + 1][l1] + 1e-8f;
            float dz = v1.z - s_mT[d0 + 2][l1] + 1e-8f;
            float dw = v1.w - s_mT[d0 + 3][l1] + 1e-8f;
            p1 = fmaf(dx, dx, fmaf(dy, dy, fmaf(dz, dz, dw * dw)));
        }
        if (a2) {
            float dx = v2.x - s_mT[d0 + 0][l2] + 1e-8f;
            float dy = v2.y - s_mT[d0 + 1][l2] + 1e-8f;
            float dz = v2.z - s_mT[d0 + 2][l2] + 1e-8f;
            float dw = v2.w - s_mT[d0 + 3][l2] + 1e-8f;
            p2 = fmaf(dx, dx, fmaf(dy, dy, fmaf(dz, dz, dw * dw)));
        }
        p1 += __shfl_xor_sync(0xffffffffu, p1, 1);
        p1 += __shfl_xor_sync(0xffffffffu, p1, 2);
        p2 += __shfl_xor_sync(0xffffffffu, p2, 1);
        p2 += __shfl_xor_sync(0xffffffffu, p2, 2);
        if (g == 0) {
            if (a1) {
                float h = fmaxf(sqrtf(p1) - 0.5f, 0.f);
                local += h * h * s_inv[l1];
            }
            if (a2) {
                float h = fmaxf(sqrtf(p2) - 0.5f, 0.f);
                local += h * h * s_inv[l2];
            }
        }
    }

    #pragma unroll
    for (int o = 16; o > 0; o >>= 1)
        local += __shfl_xor_sync(0xffffffffu, local, o);
    if (lane == 0) s_w[threadIdx.x >> 5] = local;
    __syncthreads();
    if (threadIdx.x == 0) {
        float s = 0.f;
        #pragma unroll
        for (int w = 0; w < 8; w++) s += s_w[w];
        red_add_f32(&g_var, s);
    }
}

// ---------------------------------------------------------------- finalize (1 block, 256 thr)
__global__ void k_final(float* __restrict__ out) {
    __shared__ float s_m[C_CLUST][16];
    __shared__ float s_red[256];
    int t = threadIdx.x;
    for (int i = t; i < C_CLUST * 16; i += 256)
        ((float*)s_m)[i] = g_means[i];
    __syncthreads();

    float regp = 0.f;
    if (t < C_CLUST) {
        float s = 0.f;
        #pragma unroll
        for (int d = 0; d < 16; d++) {
            float v = s_m[t][d] + 1e-8f;
            s += v * v;
        }
        regp = sqrtf(s);
    }

    float dl = 0.f;
    for (int p = t; p < C_CLUST * C_CLUST; p += 256) {
        int i = p >> 6, jj = p & 63;
        if (i != jj) {
            float s = 0.f;
            #pragma unroll
            for (int d = 0; d < 16; d++) {
                float df = s_m[i][d] - s_m[jj][d] + 1e-8f;
                s += df * df;
            }
            float pd = sqrtf(s);
            float h = fmaxf(3.0f - pd, 0.f);   // 2 * DELTA_DIST
            dl += h * h;
        }
    }

    s_red[t] = dl; __syncthreads();
    for (int o = 128; o > 0; o >>= 1) { if (t < o) s_red[t] += s_red[t + o]; __syncthreads(); }
    float dist_loss = s_red[0] / (float)(C_CLUST * (C_CLUST - 1));
    __syncthreads();

    s_red[t] = regp; __syncthreads();
    for (int o = 128; o > 0; o >>= 1) { if (t < o) s_red[t] += s_red[t + o]; __syncthreads(); }
    float reg_loss = s_red[0] / (float)C_CLUST;

    if (t == 0) {
        float var_loss = g_var;
        out[0] = var_loss + dist_loss + 0.001f * reg_loss;
        out[1] = var_loss;
        out[2] = dist_loss;
        out[3] = reg_loss;
    }
}

// ---------------------------------------------------------------- launch
extern "C" void kernel_launch(void* const* d_in, const int* in_sizes, int n_in,
                              void* d_out, int out_size) {
    const float*  feat   = (const float*)d_in[0];
    const int*    labels = (const int*)d_in[1];
    int N  = in_sizes[1];     // number of points
    int n4 = N * 4;           // float4 count (D=16)

    void* accPtr = nullptr;
    cudaGetSymbolAddress(&accPtr, g_acc);
    cudaMemsetAsync(accPtr, 0, sizeof(float) * NCOPY * ACC_SIZE);

    k_pass1<<<P1_BLOCKS, 128>>>(feat, labels, N);
    k_means<<<1, 1024>>>();
    k_pass2<<<148 * 8, 256>>>((const float4*)feat, labels, n4);
    k_final<<<1, 256>>>((float*)d_out);
}